// round 6
// baseline (speedup 1.0000x reference)
#include <cuda_runtime.h>
#include <stdint.h>
#include <math.h>

// ---------------- problem constants ----------------------------------------
#define BB   8
#define CC   512
#define SS   256
#define TT   8192
#define DIL  4
#define NTOT (BB*TT)       // 65536
#define K1   (2*CC)        // 1024 reduction dim GEMM1
#define M1   (2*CC)        // 1024 rows of W1 (F/G interleaved)
#define M2   (CC+SS)       // 768 rows GEMM2
#define KC   32            // k floats per smem stage
#define AST  36            // padded smem row stride (floats)
#define SQRT_HALF 0.70710678118654752440f

// ---------------- device scratch --------------------------------------------
__device__ __align__(16) float g_xT[(size_t)NTOT*CC];  // [b][t][c], tf32-rounded
__device__ __align__(16) float g_zT[(size_t)NTOT*CC];  // [b][t][c], tf32-rounded
__device__ __align__(16) float g_W1[M1*K1];            // [o=2c+g][k]
__device__ __align__(16) float g_W2[M2*CC];            // [m][k]
__device__ __align__(16) float g_zero[16];             // zero-initialized (causal pad)

// ---------------- helpers ----------------------------------------------------
__device__ __forceinline__ float tf32r(float x) {
    uint32_t u;
    asm("cvt.rna.tf32.f32 %0, %1;" : "=r"(u) : "f"(x));
    return __uint_as_float(u);
}
__device__ __forceinline__ void mma8(float* c, const uint32_t* a, const uint32_t* b) {
    asm volatile(
        "mma.sync.aligned.m16n8k8.row.col.f32.tf32.tf32.f32 "
        "{%0,%1,%2,%3}, {%4,%5,%6,%7}, {%8,%9}, {%0,%1,%2,%3};"
        : "+f"(c[0]), "+f"(c[1]), "+f"(c[2]), "+f"(c[3])
        : "r"(a[0]), "r"(a[1]), "r"(a[2]), "r"(a[3]), "r"(b[0]), "r"(b[1]));
}
__device__ __forceinline__ void cpa16(uint32_t dst, const void* src) {
    asm volatile("cp.async.cg.shared.global [%0], [%1], 16;" :: "r"(dst), "l"(src));
}
#define CP_COMMIT() asm volatile("cp.async.commit_group;" ::: "memory")
#define CP_WAIT0()  asm volatile("cp.async.wait_group 0;" ::: "memory")

#define STAGE_A (128*AST)          // floats
#define STAGE_B (256*AST)
#define SMEM_DYN ((2*STAGE_A + 2*STAGE_B) * 4)

// ---------------- transpose + pack ------------------------------------------
__global__ void transpose_x(const float* __restrict__ x) {
    __shared__ float tile[32][33];
    const int b = blockIdx.z, c0 = blockIdx.y * 32, t0 = blockIdx.x * 32;
    const int tx = threadIdx.x, ty = threadIdx.y;
    const float* xb = x + ((size_t)b * CC + c0) * TT + t0;
    #pragma unroll
    for (int i = 0; i < 4; i++) tile[ty + 8 * i][tx] = xb[(ty + 8 * i) * TT + tx];
    __syncthreads();
    float* xt = g_xT + ((size_t)b * TT + t0) * CC + c0;
    #pragma unroll
    for (int i = 0; i < 4; i++) xt[(ty + 8 * i) * CC + tx] = tf32r(tile[tx][ty + 8 * i]);
}
__global__ void pack_w1(const float* __restrict__ fw, const float* __restrict__ gw) {
    int idx = blockIdx.x * blockDim.x + threadIdx.x;
    if (idx >= M1 * K1) return;
    int o = idx / K1, k = idx % K1;
    int co = o >> 1, ci = k & (CC - 1);
    int tap = (k < CC) ? 1 : 0;     // k<512: x[t], k>=512: x[t-4]
    const float* w = (o & 1) ? gw : fw;
    g_W1[idx] = tf32r(w[(co * CC + ci) * 2 + tap]);
}
__global__ void pack_w2(const float* __restrict__ rw, const float* __restrict__ sw) {
    int idx = blockIdx.x * blockDim.x + threadIdx.x;
    if (idx >= M2 * CC) return;
    int m = idx / CC, k = idx % CC;
    g_W2[idx] = tf32r((m < CC) ? rw[m * CC + k] : sw[(m - CC) * CC + k]);
}

// ---------------- GEMM1: D[t][2c+g] = xT2 @ W1^T, fused gating --------------
// CTA 128(t) x 256(interleaved outch); 8 warps 2x4; warp tile 64x64.
__global__ void __launch_bounds__(256, 1)
gemm1(const float* __restrict__ fbias, const float* __restrict__ gbias)
{
    extern __shared__ float dsm[];
    float* sA = dsm;                    // [2][128*AST]
    float* sB = dsm + 2 * STAGE_A;      // [2][256*AST]

    const int tid = threadIdx.x, lane = tid & 31, wid = tid >> 5;
    const int wm = wid >> 2, wn = wid & 3;
    const int nb = blockIdx.x;                    // 4 outch-tiles (256 wide)
    const int tb = blockIdx.y;                    // 512 t-tiles (128 tall)
    const int base = tb * 128;
    const int b = base / TT;
    const int t0 = base % TT;
    const int n0 = nb * 256;
    const float* __restrict__ xTb = g_xT + (size_t)b * TT * CC;

    const uint32_t sA_u = (uint32_t)__cvta_generic_to_shared(sA);
    const uint32_t sB_u = (uint32_t)__cvta_generic_to_shared(sB);

    float acc[4][8][4];
    #pragma unroll
    for (int i = 0; i < 4; i++)
        #pragma unroll
        for (int j = 0; j < 8; j++)
            #pragma unroll
            for (int q = 0; q < 4; q++) acc[i][j][q] = 0.f;

    const int arow = tid >> 3, ac4 = tid & 7;
    auto issueA = [&](int st, int k0) {
        const int sh = (k0 >= CC) ? DIL : 0;
        const int kk = k0 & (CC - 1);
        #pragma unroll
        for (int i = 0; i < 4; i++) {
            int row = arow + i * 32;
            int t = t0 + row - sh;
            const float* src = (t >= 0) ? &xTb[(size_t)t * CC + kk + ac4 * 4]
                                        : &g_zero[0];
            cpa16(sA_u + (st * STAGE_A + row * AST + ac4 * 4) * 4, src);
        }
    };
    auto issueB = [&](int st, int k0) {
        #pragma unroll
        for (int i = 0; i < 8; i++) {
            int row = arow + i * 32;
            cpa16(sB_u + (st * STAGE_B + row * AST + ac4 * 4) * 4,
                  &g_W1[(size_t)(n0 + row) * K1 + k0 + ac4 * 4]);
        }
    };

    issueA(0, 0); issueB(0, 0); CP_COMMIT();

    const float* aP[2] = { sA + (wm * 64 + (lane >> 2)) * AST + (lane & 3),
                           sA + STAGE_A + (wm * 64 + (lane >> 2)) * AST + (lane & 3) };
    const float* bP[2] = { sB + (wn * 64 + (lane >> 2)) * AST + (lane & 3),
                           sB + STAGE_B + (wn * 64 + (lane >> 2)) * AST + (lane & 3) };

    const int NC = K1 / KC;   // 32
    for (int c = 0; c < NC; c++) {
        const int st = c & 1;
        CP_WAIT0();
        __syncthreads();
        if (c + 1 < NC) { issueA(st ^ 1, (c + 1) * KC); issueB(st ^ 1, (c + 1) * KC); CP_COMMIT(); }
        const float* a = aP[st];
        const float* bs = bP[st];
        #pragma unroll
        for (int ks = 0; ks < 4; ks++) {
            const int kc = ks * 8;
            uint32_t af[4][4], bf[8][2];
            #pragma unroll
            for (int mi = 0; mi < 4; mi++) {
                const float* p = a + mi * 16 * AST + kc;
                af[mi][0] = __float_as_uint(p[0]);
                af[mi][1] = __float_as_uint(p[8 * AST]);
                af[mi][2] = __float_as_uint(p[4]);
                af[mi][3] = __float_as_uint(p[8 * AST + 4]);
            }
            #pragma unroll
            for (int ni = 0; ni < 8; ni++) {
                const float* p = bs + ni * 8 * AST + kc;
                bf[ni][0] = __float_as_uint(p[0]);
                bf[ni][1] = __float_as_uint(p[4]);
            }
            #pragma unroll
            for (int mi = 0; mi < 4; mi++)
                #pragma unroll
                for (int ni = 0; ni < 8; ni++)
                    mma8(acc[mi][ni], af[mi], bf[ni]);
        }
        __syncthreads();
    }

    // ---- epilogue: (c0,c1)=(F,G) at row t; (c2,c3) at t+8 -------------------
    float* __restrict__ zb = g_zT + (size_t)b * TT * CC;
    #pragma unroll
    for (int mi = 0; mi < 4; mi++) {
        const int t_lo = t0 + wm * 64 + mi * 16 + (lane >> 2);
        #pragma unroll
        for (int ni = 0; ni < 8; ni++) {
            const int ch = nb * 128 + wn * 32 + ni * 4 + (lane & 3);
            const float fb = fbias[ch], gb = gbias[ch];
            float F0 = acc[mi][ni][0] + fb;
            float G0 = acc[mi][ni][1] + gb;
            float F1 = acc[mi][ni][2] + fb;
            float G1 = acc[mi][ni][3] + gb;
            zb[(size_t)t_lo * CC + ch] =
                tf32r(tanhf(F0) * (1.f / (1.f + __expf(-G0))));
            zb[(size_t)(t_lo + 8) * CC + ch] =
                tf32r(tanhf(F1) * (1.f / (1.f + __expf(-G1))));
        }
    }
}

// ---------------- GEMM2: D[m][t] = W2 @ zT^T, fused residual/skip -----------
// CTA 128(m) x 256(t); 8 warps 2x4; warp tile 64x64.
__global__ void __launch_bounds__(256, 1)
gemm2(const float* __restrict__ x,
      const float* __restrict__ rbias, const float* __restrict__ sbias,
      float* __restrict__ out)
{
    extern __shared__ float dsm[];
    float* sA = dsm;
    float* sB = dsm + 2 * STAGE_A;

    const int tid = threadIdx.x, lane = tid & 31, wid = tid >> 5;
    const int wm = wid >> 2, wn = wid & 3;
    const int mb = blockIdx.x;                    // 6 m-tiles (128)
    const int tb = blockIdx.y;                    // 256 t-tiles (256 wide)
    const int base = tb * 256;
    const int b = base / TT;
    const int t0 = base % TT;
    const int m0 = mb * 128;
    const float* __restrict__ zTb = g_zT + (size_t)b * TT * CC;

    const uint32_t sA_u = (uint32_t)__cvta_generic_to_shared(sA);
    const uint32_t sB_u = (uint32_t)__cvta_generic_to_shared(sB);

    float acc[4][8][4];
    #pragma unroll
    for (int i = 0; i < 4; i++)
        #pragma unroll
        for (int j = 0; j < 8; j++)
            #pragma unroll
            for (int q = 0; q < 4; q++) acc[i][j][q] = 0.f;

    const int arow = tid >> 3, ac4 = tid & 7;
    auto issueA = [&](int st, int k0) {          // W2 rows (m)
        #pragma unroll
        for (int i = 0; i < 4; i++) {
            int row = arow + i * 32;
            cpa16(sA_u + (st * STAGE_A + row * AST + ac4 * 4) * 4,
                  &g_W2[(size_t)(m0 + row) * CC + k0 + ac4 * 4]);
        }
    };
    auto issueB = [&](int st, int k0) {          // zT rows (t)
        #pragma unroll
        for (int i = 0; i < 8; i++) {
            int row = arow + i * 32;
            cpa16(sB_u + (st * STAGE_B + row * AST + ac4 * 4) * 4,
                  &zTb[(size_t)(t0 + row) * CC + k0 + ac4 * 4]);
        }
    };

    issueA(0, 0); issueB(0, 0); CP_COMMIT();

    const float* aP[2] = { sA + (wm * 64 + (lane >> 2)) * AST + (lane & 3),
                           sA + STAGE_A + (wm * 64 + (lane >> 2)) * AST + (lane & 3) };
    const float* bP[2] = { sB + (wn * 64 + (lane >> 2)) * AST + (lane & 3),
                           sB + STAGE_B + (wn * 64 + (lane >> 2)) * AST + (lane & 3) };

    const int NC = CC / KC;   // 16
    for (int c = 0; c < NC; c++) {
        const int st = c & 1;
        CP_WAIT0();
        __syncthreads();
        if (c + 1 < NC) { issueA(st ^ 1, (c + 1) * KC); issueB(st ^ 1, (c + 1) * KC); CP_COMMIT(); }
        const float* a = aP[st];
        const float* bs = bP[st];
        #pragma unroll
        for (int ks = 0; ks < 4; ks++) {
            const int kc = ks * 8;
            uint32_t af[4][4], bf[8][2];
            #pragma unroll
            for (int mi = 0; mi < 4; mi++) {
                const float* p = a + mi * 16 * AST + kc;
                af[mi][0] = __float_as_uint(p[0]);
                af[mi][1] = __float_as_uint(p[8 * AST]);
                af[mi][2] = __float_as_uint(p[4]);
                af[mi][3] = __float_as_uint(p[8 * AST + 4]);
            }
            #pragma unroll
            for (int ni = 0; ni < 8; ni++) {
                const float* p = bs + ni * 8 * AST + kc;
                bf[ni][0] = __float_as_uint(p[0]);
                bf[ni][1] = __float_as_uint(p[4]);
            }
            #pragma unroll
            for (int mi = 0; mi < 4; mi++)
                #pragma unroll
                for (int ni = 0; ni < 8; ni++)
                    mma8(acc[mi][ni], af[mi], bf[ni]);
        }
        __syncthreads();
    }

    // ---- epilogue: rows m, cols t; (c0,c1) = adjacent t pair ----------------
    #pragma unroll
    for (int mi = 0; mi < 4; mi++) {
        #pragma unroll
        for (int half = 0; half < 2; half++) {
            const int m = m0 + wm * 64 + mi * 16 + (lane >> 2) + half * 8;
            if (m < CC) {
                const float rbv = rbias[m];
                const float* __restrict__ xrow = x + ((size_t)b * CC + m) * TT;
                float* __restrict__ orow = out + ((size_t)b * CC + m) * TT;
                #pragma unroll
                for (int ni = 0; ni < 8; ni++) {
                    const int t = t0 + wn * 64 + ni * 8 + (lane & 3) * 2;
                    float2 xv = *(const float2*)&xrow[t];
                    float2 o;
                    o.x = (xv.x + acc[mi][ni][half * 2]     + rbv) * SQRT_HALF;
                    o.y = (xv.y + acc[mi][ni][half * 2 + 1] + rbv) * SQRT_HALF;
                    *(float2*)&orow[t] = o;
                }
            } else {
                const int s = m - CC;
                const float sbv = sbias[s];
                float* __restrict__ orow =
                    out + (size_t)BB * CC * TT + ((size_t)b * SS + s) * TT;
                #pragma unroll
                for (int ni = 0; ni < 8; ni++) {
                    const int t = t0 + wn * 64 + ni * 8 + (lane & 3) * 2;
                    float2 o;
                    o.x = acc[mi][ni][half * 2]     + sbv;
                    o.y = acc[mi][ni][half * 2 + 1] + sbv;
                    *(float2*)&orow[t] = o;
                }
            }
        }
    }
}

// ---------------- launch -----------------------------------------------------
extern "C" void kernel_launch(void* const* d_in, const int* in_sizes, int n_in,
                              void* d_out, int out_size)
{
    const float* x  = (const float*)d_in[0];
    const float* fw = (const float*)d_in[1];
    const float* fb = (const float*)d_in[2];
    const float* gw = (const float*)d_in[3];
    const float* gb = (const float*)d_in[4];
    const float* rw = (const float*)d_in[5];
    const float* rb = (const float*)d_in[6];
    const float* sw = (const float*)d_in[7];
    const float* sb = (const float*)d_in[8];
    float* out = (float*)d_out;

    cudaFuncSetAttribute(gemm1, cudaFuncAttributeMaxDynamicSharedMemorySize, SMEM_DYN);
    cudaFuncSetAttribute(gemm2, cudaFuncAttributeMaxDynamicSharedMemorySize, SMEM_DYN);

    transpose_x<<<dim3(TT / 32, CC / 32, BB), dim3(32, 8)>>>(x);
    pack_w1<<<(M1 * K1 + 255) / 256, 256>>>(fw, gw);
    pack_w2<<<(M2 * CC + 255) / 256, 256>>>(rw, sw);
    gemm1<<<dim3(M1 / 256, NTOT / 128), 256, SMEM_DYN>>>(fb, gb);
    gemm2<<<dim3(M2 / 128, NTOT / 256), 256, SMEM_DYN>>>(x, rb, sb, out);
}

// round 7
// speedup vs baseline: 1.1862x; 1.1862x over previous
#include <cuda_runtime.h>
#include <stdint.h>
#include <math.h>

// ---------------- problem constants ----------------------------------------
#define BB   8
#define CC   512
#define SS   256
#define TT   8192
#define DIL  4
#define NTOT (BB*TT)       // 65536
#define K1   (2*CC)        // 1024 reduction dim GEMM1
#define M1   (2*CC)        // 1024 rows of W1 (F/G interleaved)
#define M2   (CC+SS)       // 768 rows GEMM2
#define KC   32            // k floats per smem stage
#define AST  36            // padded smem row stride (floats)
#define NST  3             // pipeline stages
#define SQRT_HALF 0.70710678118654752440f

// ---------------- device scratch --------------------------------------------
__device__ __align__(16) float g_xT[(size_t)NTOT*CC];  // [b][t][c], tf32-rounded
__device__ __align__(16) float g_zT[(size_t)NTOT*CC];  // [b][t][c], tf32-rounded
__device__ __align__(16) float g_W1[M1*K1];            // [o=2c+g][k]
__device__ __align__(16) float g_W2[M2*CC];            // [m][k]
__device__ __align__(16) float g_zero[16];             // zero-initialized (causal pad)

// ---------------- helpers ----------------------------------------------------
__device__ __forceinline__ float tf32r(float x) {
    uint32_t u;
    asm("cvt.rna.tf32.f32 %0, %1;" : "=r"(u) : "f"(x));
    return __uint_as_float(u);
}
__device__ __forceinline__ void mma8(float* c, const uint32_t* a, const uint32_t* b) {
    asm volatile(
        "mma.sync.aligned.m16n8k8.row.col.f32.tf32.tf32.f32 "
        "{%0,%1,%2,%3}, {%4,%5,%6,%7}, {%8,%9}, {%0,%1,%2,%3};"
        : "+f"(c[0]), "+f"(c[1]), "+f"(c[2]), "+f"(c[3])
        : "r"(a[0]), "r"(a[1]), "r"(a[2]), "r"(a[3]), "r"(b[0]), "r"(b[1]));
}
__device__ __forceinline__ void cpa16(uint32_t dst, const void* src) {
    asm volatile("cp.async.cg.shared.global [%0], [%1], 16;" :: "r"(dst), "l"(src));
}
#define CP_COMMIT() asm volatile("cp.async.commit_group;" ::: "memory")
#define CP_WAIT1()  asm volatile("cp.async.wait_group 1;" ::: "memory")

#define STAGE (128*AST)                       // floats per (A or B) stage
#define SMEM_DYN (2*NST*STAGE*4)              // A[NST] + B[NST]

// ---------------- transpose + pack ------------------------------------------
__global__ void transpose_x(const float* __restrict__ x) {
    __shared__ float tile[32][33];
    const int b = blockIdx.z, c0 = blockIdx.y * 32, t0 = blockIdx.x * 32;
    const int tx = threadIdx.x, ty = threadIdx.y;
    const float* xb = x + ((size_t)b * CC + c0) * TT + t0;
    #pragma unroll
    for (int i = 0; i < 4; i++) tile[ty + 8 * i][tx] = xb[(ty + 8 * i) * TT + tx];
    __syncthreads();
    float* xt = g_xT + ((size_t)b * TT + t0) * CC + c0;
    #pragma unroll
    for (int i = 0; i < 4; i++) xt[(ty + 8 * i) * CC + tx] = tf32r(tile[tx][ty + 8 * i]);
}
__global__ void pack_w1(const float* __restrict__ fw, const float* __restrict__ gw) {
    int idx = blockIdx.x * blockDim.x + threadIdx.x;
    if (idx >= M1 * K1) return;
    int o = idx / K1, k = idx % K1;
    int co = o >> 1, ci = k & (CC - 1);
    int tap = (k < CC) ? 1 : 0;     // k<512: x[t], k>=512: x[t-4]
    const float* w = (o & 1) ? gw : fw;
    g_W1[idx] = tf32r(w[(co * CC + ci) * 2 + tap]);
}
__global__ void pack_w2(const float* __restrict__ rw, const float* __restrict__ sw) {
    int idx = blockIdx.x * blockDim.x + threadIdx.x;
    if (idx >= M2 * CC) return;
    int m = idx / CC, k = idx % CC;
    g_W2[idx] = tf32r((m < CC) ? rw[m * CC + k] : sw[(m - CC) * CC + k]);
}

// ---------------- GEMM1: D[t][2c+g] = xT2 @ W1^T, fused gating --------------
// CTA 128(t) x 128(interleaved outch); 8 warps 2x4; warp tile 64x32.
__global__ void __launch_bounds__(256, 2)
gemm1(const float* __restrict__ fbias, const float* __restrict__ gbias)
{
    extern __shared__ float dsm[];
    float* sA = dsm;                    // [NST][128*AST]
    float* sB = dsm + NST * STAGE;      // [NST][128*AST]

    const int tid = threadIdx.x, lane = tid & 31, wid = tid >> 5;
    const int wm = wid >> 2, wn = wid & 3;
    const int nb = blockIdx.x;                    // 8 outch-tiles (128 wide)
    const int tb = blockIdx.y;                    // 512 t-tiles (128 tall)
    const int base = tb * 128;
    const int b = base / TT;
    const int t0 = base % TT;
    const int n0 = nb * 128;
    const float* __restrict__ xTb = g_xT + (size_t)b * TT * CC;

    const uint32_t sA_u = (uint32_t)__cvta_generic_to_shared(sA);
    const uint32_t sB_u = (uint32_t)__cvta_generic_to_shared(sB);

    float acc[4][4][4];
    #pragma unroll
    for (int i = 0; i < 4; i++)
        #pragma unroll
        for (int j = 0; j < 4; j++)
            #pragma unroll
            for (int q = 0; q < 4; q++) acc[i][j][q] = 0.f;

    const int arow = tid >> 3, ac4 = tid & 7;
    auto issue = [&](int st, int k0) {
        const int sh = (k0 >= CC) ? DIL : 0;
        const int kk = k0 & (CC - 1);
        #pragma unroll
        for (int i = 0; i < 4; i++) {
            int row = arow + i * 32;
            int t = t0 + row - sh;
            const float* srcA = (t >= 0) ? &xTb[(size_t)t * CC + kk + ac4 * 4]
                                         : &g_zero[0];
            cpa16(sA_u + (st * STAGE + row * AST + ac4 * 4) * 4, srcA);
            cpa16(sB_u + (st * STAGE + row * AST + ac4 * 4) * 4,
                  &g_W1[(size_t)(n0 + row) * K1 + k0 + ac4 * 4]);
        }
    };

    issue(0, 0);      CP_COMMIT();
    issue(1, KC);     CP_COMMIT();

    const int aoff = (wm * 64 + (lane >> 2)) * AST + (lane & 3);
    const int boff = (wn * 32 + (lane >> 2)) * AST + (lane & 3);

    const int NC = K1 / KC;   // 32
    int st = 0;
    for (int c = 0; c < NC; c++) {
        CP_WAIT1();
        __syncthreads();
        const float* a  = sA + st * STAGE + aoff;
        const float* bs = sB + st * STAGE + boff;
        #pragma unroll
        for (int ks = 0; ks < 4; ks++) {
            const int kc = ks * 8;
            uint32_t af[4][4], bf[4][2];
            #pragma unroll
            for (int mi = 0; mi < 4; mi++) {
                const float* p = a + mi * 16 * AST + kc;
                af[mi][0] = __float_as_uint(p[0]);
                af[mi][1] = __float_as_uint(p[8 * AST]);
                af[mi][2] = __float_as_uint(p[4]);
                af[mi][3] = __float_as_uint(p[8 * AST + 4]);
            }
            #pragma unroll
            for (int ni = 0; ni < 4; ni++) {
                const float* p = bs + ni * 8 * AST + kc;
                bf[ni][0] = __float_as_uint(p[0]);
                bf[ni][1] = __float_as_uint(p[4]);
            }
            #pragma unroll
            for (int mi = 0; mi < 4; mi++)
                #pragma unroll
                for (int ni = 0; ni < 4; ni++)
                    mma8(acc[mi][ni], af[mi], bf[ni]);
        }
        __syncthreads();
        if (c + 2 < NC) issue((c + 2) % NST, (c + 2) * KC);
        CP_COMMIT();
        st = (st + 1) % NST;
    }

    // ---- epilogue: (c0,c1)=(F,G) at row t; (c2,c3) at t+8 -------------------
    float* __restrict__ zb = g_zT + (size_t)b * TT * CC;
    #pragma unroll
    for (int mi = 0; mi < 4; mi++) {
        const int t_lo = t0 + wm * 64 + mi * 16 + (lane >> 2);
        #pragma unroll
        for (int ni = 0; ni < 4; ni++) {
            const int ch = (n0 >> 1) + wn * 16 + ni * 4 + (lane & 3);
            const float fb = fbias[ch], gb = gbias[ch];
            float F0 = acc[mi][ni][0] + fb;
            float G0 = acc[mi][ni][1] + gb;
            float F1 = acc[mi][ni][2] + fb;
            float G1 = acc[mi][ni][3] + gb;
            zb[(size_t)t_lo * CC + ch] =
                tf32r(tanhf(F0) * (1.f / (1.f + __expf(-G0))));
            zb[(size_t)(t_lo + 8) * CC + ch] =
                tf32r(tanhf(F1) * (1.f / (1.f + __expf(-G1))));
        }
    }
}

// ---------------- GEMM2: D[m][t] = W2 @ zT^T, fused residual/skip -----------
// CTA 128(m) x 128(t); 8 warps 2x4; warp tile 64x32.
__global__ void __launch_bounds__(256, 2)
gemm2(const float* __restrict__ x,
      const float* __restrict__ rbias, const float* __restrict__ sbias,
      float* __restrict__ out)
{
    extern __shared__ float dsm[];
    float* sA = dsm;
    float* sB = dsm + NST * STAGE;

    const int tid = threadIdx.x, lane = tid & 31, wid = tid >> 5;
    const int wm = wid >> 2, wn = wid & 3;
    const int mb = blockIdx.x;                    // 6 m-tiles (128)
    const int tb = blockIdx.y;                    // 512 t-tiles (128 wide)
    const int base = tb * 128;
    const int b = base / TT;
    const int t0 = base % TT;
    const int m0 = mb * 128;
    const float* __restrict__ zTb = g_zT + (size_t)b * TT * CC;

    const uint32_t sA_u = (uint32_t)__cvta_generic_to_shared(sA);
    const uint32_t sB_u = (uint32_t)__cvta_generic_to_shared(sB);

    float acc[4][4][4];
    #pragma unroll
    for (int i = 0; i < 4; i++)
        #pragma unroll
        for (int j = 0; j < 4; j++)
            #pragma unroll
            for (int q = 0; q < 4; q++) acc[i][j][q] = 0.f;

    const int arow = tid >> 3, ac4 = tid & 7;
    auto issue = [&](int st, int k0) {
        #pragma unroll
        for (int i = 0; i < 4; i++) {
            int row = arow + i * 32;
            cpa16(sA_u + (st * STAGE + row * AST + ac4 * 4) * 4,
                  &g_W2[(size_t)(m0 + row) * CC + k0 + ac4 * 4]);
            cpa16(sB_u + (st * STAGE + row * AST + ac4 * 4) * 4,
                  &zTb[(size_t)(t0 + row) * CC + k0 + ac4 * 4]);
        }
    };

    issue(0, 0);      CP_COMMIT();
    issue(1, KC);     CP_COMMIT();

    const int aoff = (wm * 64 + (lane >> 2)) * AST + (lane & 3);
    const int boff = (wn * 32 + (lane >> 2)) * AST + (lane & 3);

    const int NC = CC / KC;   // 16
    int st = 0;
    for (int c = 0; c < NC; c++) {
        CP_WAIT1();
        __syncthreads();
        const float* a  = sA + st * STAGE + aoff;
        const float* bs = sB + st * STAGE + boff;
        #pragma unroll
        for (int ks = 0; ks < 4; ks++) {
            const int kc = ks * 8;
            uint32_t af[4][4], bf[4][2];
            #pragma unroll
            for (int mi = 0; mi < 4; mi++) {
                const float* p = a + mi * 16 * AST + kc;
                af[mi][0] = __float_as_uint(p[0]);
                af[mi][1] = __float_as_uint(p[8 * AST]);
                af[mi][2] = __float_as_uint(p[4]);
                af[mi][3] = __float_as_uint(p[8 * AST + 4]);
            }
            #pragma unroll
            for (int ni = 0; ni < 4; ni++) {
                const float* p = bs + ni * 8 * AST + kc;
                bf[ni][0] = __float_as_uint(p[0]);
                bf[ni][1] = __float_as_uint(p[4]);
            }
            #pragma unroll
            for (int mi = 0; mi < 4; mi++)
                #pragma unroll
                for (int ni = 0; ni < 4; ni++)
                    mma8(acc[mi][ni], af[mi], bf[ni]);
        }
        __syncthreads();
        if (c + 2 < NC) issue((c + 2) % NST, (c + 2) * KC);
        CP_COMMIT();
        st = (st + 1) % NST;
    }

    // ---- epilogue: rows m (channels), cols t ---------------------------------
    #pragma unroll
    for (int mi = 0; mi < 4; mi++) {
        #pragma unroll
        for (int half = 0; half < 2; half++) {
            const int m = m0 + wm * 64 + mi * 16 + (lane >> 2) + half * 8;
            if (m < CC) {
                const float rbv = rbias[m];
                const float* __restrict__ xrow = x + ((size_t)b * CC + m) * TT;
                float* __restrict__ orow = out + ((size_t)b * CC + m) * TT;
                #pragma unroll
                for (int ni = 0; ni < 4; ni++) {
                    const int t = t0 + wn * 32 + ni * 8 + (lane & 3) * 2;
                    float2 xv = *(const float2*)&xrow[t];
                    float2 o;
                    o.x = (xv.x + acc[mi][ni][half * 2]     + rbv) * SQRT_HALF;
                    o.y = (xv.y + acc[mi][ni][half * 2 + 1] + rbv) * SQRT_HALF;
                    *(float2*)&orow[t] = o;
                }
            } else {
                const int s = m - CC;
                const float sbv = sbias[s];
                float* __restrict__ orow =
                    out + (size_t)BB * CC * TT + ((size_t)b * SS + s) * TT;
                #pragma unroll
                for (int ni = 0; ni < 4; ni++) {
                    const int t = t0 + wn * 32 + ni * 8 + (lane & 3) * 2;
                    float2 o;
                    o.x = acc[mi][ni][half * 2]     + sbv;
                    o.y = acc[mi][ni][half * 2 + 1] + sbv;
                    *(float2*)&orow[t] = o;
                }
            }
        }
    }
}

// ---------------- launch -----------------------------------------------------
extern "C" void kernel_launch(void* const* d_in, const int* in_sizes, int n_in,
                              void* d_out, int out_size)
{
    const float* x  = (const float*)d_in[0];
    const float* fw = (const float*)d_in[1];
    const float* fb = (const float*)d_in[2];
    const float* gw = (const float*)d_in[3];
    const float* gb = (const float*)d_in[4];
    const float* rw = (const float*)d_in[5];
    const float* rb = (const float*)d_in[6];
    const float* sw = (const float*)d_in[7];
    const float* sb = (const float*)d_in[8];
    float* out = (float*)d_out;

    cudaFuncSetAttribute(gemm1, cudaFuncAttributeMaxDynamicSharedMemorySize, SMEM_DYN);
    cudaFuncSetAttribute(gemm2, cudaFuncAttributeMaxDynamicSharedMemorySize, SMEM_DYN);

    transpose_x<<<dim3(TT / 32, CC / 32, BB), dim3(32, 8)>>>(x);
    pack_w1<<<(M1 * K1 + 255) / 256, 256>>>(fw, gw);
    pack_w2<<<(M2 * CC + 255) / 256, 256>>>(rw, sw);
    gemm1<<<dim3(M1 / 128, NTOT / 128), 256, SMEM_DYN>>>(fb, gb);
    gemm2<<<dim3(M2 / 128, NTOT / 128), 256, SMEM_DYN>>>(x, rb, sb, out);
}

// round 9
// speedup vs baseline: 2.1093x; 1.7782x over previous
#include <cuda_runtime.h>
#include <cuda_fp16.h>
#include <stdint.h>
#include <math.h>

// ---------------- problem constants ----------------------------------------
#define BB   8
#define CC   512
#define SS   256
#define TT   8192
#define DIL  4
#define NTOT (BB*TT)       // 65536
#define K1   (2*CC)        // 1024 reduction dim GEMM1
#define M1   (2*CC)        // 1024 rows of W1 (F/G interleaved)
#define M2   (CC+SS)       // 768 rows GEMM2
#define KC   64            // k halfs per smem stage (4 mma k-steps of 16)
#define HST  72            // smem row stride in halfs (144B): conflict-free
#define NST  3             // pipeline stages
#define SQRT_HALF 0.70710678118654752440f

// ---------------- device scratch --------------------------------------------
__device__ __align__(16) __half g_xT[(size_t)NTOT*CC];  // [b][t][c]
__device__ __align__(16) __half g_zT[(size_t)NTOT*CC];  // [b][t][c]
__device__ __align__(16) __half g_W1[M1*K1];            // [o=2c+g][k]
__device__ __align__(16) __half g_W2[M2*CC];            // [m][k]
__device__ __align__(16) __half g_zero[16];             // zero-init (causal pad)

// ---------------- helpers ----------------------------------------------------
__device__ __forceinline__ void mma16(float* c, const uint32_t* a, const uint32_t* b) {
    asm volatile(
        "mma.sync.aligned.m16n8k16.row.col.f32.f16.f16.f32 "
        "{%0,%1,%2,%3}, {%4,%5,%6,%7}, {%8,%9}, {%0,%1,%2,%3};"
        : "+f"(c[0]), "+f"(c[1]), "+f"(c[2]), "+f"(c[3])
        : "r"(a[0]), "r"(a[1]), "r"(a[2]), "r"(a[3]), "r"(b[0]), "r"(b[1]));
}
__device__ __forceinline__ void cpa16(uint32_t dst, const void* src) {
    asm volatile("cp.async.cg.shared.global [%0], [%1], 16;" :: "r"(dst), "l"(src));
}
#define CP_COMMIT() asm volatile("cp.async.commit_group;" ::: "memory")
#define CP_WAIT1()  asm volatile("cp.async.wait_group 1;" ::: "memory")

#define STAGE (128*HST)                     // halfs per operand stage
#define SMEM_DYN (2*NST*STAGE*2)            // bytes: A[NST] + B[NST]

// ---------------- transpose + pack ------------------------------------------
__global__ void transpose_x(const float* __restrict__ x) {
    __shared__ float tile[32][33];
    const int b = blockIdx.z, c0 = blockIdx.y * 32, t0 = blockIdx.x * 32;
    const int tx = threadIdx.x, ty = threadIdx.y;
    const float* xb = x + ((size_t)b * CC + c0) * TT + t0;
    #pragma unroll
    for (int i = 0; i < 4; i++) tile[ty + 8 * i][tx] = xb[(ty + 8 * i) * TT + tx];
    __syncthreads();
    __half* xt = g_xT + ((size_t)b * TT + t0) * CC + c0;
    #pragma unroll
    for (int i = 0; i < 4; i++)
        xt[(size_t)(ty + 8 * i) * CC + tx] = __float2half_rn(tile[tx][ty + 8 * i]);
}
__global__ void pack_w1(const float* __restrict__ fw, const float* __restrict__ gw) {
    int idx = blockIdx.x * blockDim.x + threadIdx.x;
    if (idx >= M1 * K1) return;
    int o = idx / K1, k = idx % K1;
    int co = o >> 1, ci = k & (CC - 1);
    int tap = (k < CC) ? 1 : 0;     // k<512: x[t], k>=512: x[t-4]
    const float* w = (o & 1) ? gw : fw;
    g_W1[idx] = __float2half_rn(w[(co * CC + ci) * 2 + tap]);
}
__global__ void pack_w2(const float* __restrict__ rw, const float* __restrict__ sw) {
    int idx = blockIdx.x * blockDim.x + threadIdx.x;
    if (idx >= M2 * CC) return;
    int m = idx / CC, k = idx % CC;
    g_W2[idx] = __float2half_rn((m < CC) ? rw[m * CC + k] : sw[(m - CC) * CC + k]);
}

// ---------------- GEMM1: D[t][2c+g] = xT2 @ W1^T, fused gating --------------
// CTA 128(t) x 128(interleaved outch); 8 warps 2x4; warp tile 64x32. fp16 MMA.
__global__ void __launch_bounds__(256, 2)
gemm1(const float* __restrict__ fbias, const float* __restrict__ gbias)
{
    extern __shared__ __half hsm[];
    __half* sA = hsm;                  // [NST][128*HST]
    __half* sB = hsm + NST * STAGE;

    const int tid = threadIdx.x, lane = tid & 31, wid = tid >> 5;
    const int wm = wid >> 2, wn = wid & 3;
    const int nb = blockIdx.x;                    // 8 outch-tiles
    const int tb = blockIdx.y;                    // 512 t-tiles
    const int base = tb * 128;
    const int b = base / TT;
    const int t0 = base % TT;
    const int n0 = nb * 128;
    const __half* __restrict__ xTb = g_xT + (size_t)b * TT * CC;

    const uint32_t sA_u = (uint32_t)__cvta_generic_to_shared(sA);
    const uint32_t sB_u = (uint32_t)__cvta_generic_to_shared(sB);

    float acc[4][4][4];
    #pragma unroll
    for (int i = 0; i < 4; i++)
        #pragma unroll
        for (int j = 0; j < 4; j++)
            #pragma unroll
            for (int q = 0; q < 4; q++) acc[i][j][q] = 0.f;

    const int arow = tid >> 3, ac8 = (tid & 7) * 8;   // 8 halfs = 16B per thread
    auto issue = [&](int st, int k0) {
        const int sh = (k0 >= CC) ? DIL : 0;
        const int kk = k0 & (CC - 1);
        #pragma unroll
        for (int i = 0; i < 4; i++) {
            int row = arow + i * 32;
            int t = t0 + row - sh;
            const __half* srcA = (t >= 0) ? &xTb[(size_t)t * CC + kk + ac8]
                                          : &g_zero[0];
            cpa16(sA_u + (st * STAGE + row * HST + ac8) * 2, srcA);
            cpa16(sB_u + (st * STAGE + row * HST + ac8) * 2,
                  &g_W1[(size_t)(n0 + row) * K1 + k0 + ac8]);
        }
    };

    issue(0, 0);  CP_COMMIT();
    issue(1, KC); CP_COMMIT();

    const int aoff = (wm * 64 + (lane >> 2)) * HST + (lane & 3) * 2;
    const int boff = (wn * 32 + (lane >> 2)) * HST + (lane & 3) * 2;

    const int NC = K1 / KC;   // 16
    int st = 0;
    for (int c = 0; c < NC; c++) {
        CP_WAIT1();
        __syncthreads();
        const __half* a  = sA + st * STAGE + aoff;
        const __half* bs = sB + st * STAGE + boff;
        #pragma unroll
        for (int ks = 0; ks < 4; ks++) {
            const int kc = ks * 16;
            uint32_t af[4][4], bf[4][2];
            #pragma unroll
            for (int mi = 0; mi < 4; mi++) {
                const __half* p = a + mi * 16 * HST + kc;
                af[mi][0] = *(const uint32_t*)(p);
                af[mi][1] = *(const uint32_t*)(p + 8 * HST);
                af[mi][2] = *(const uint32_t*)(p + 8);
                af[mi][3] = *(const uint32_t*)(p + 8 * HST + 8);
            }
            #pragma unroll
            for (int ni = 0; ni < 4; ni++) {
                const __half* p = bs + ni * 8 * HST + kc;
                bf[ni][0] = *(const uint32_t*)(p);
                bf[ni][1] = *(const uint32_t*)(p + 8);
            }
            #pragma unroll
            for (int mi = 0; mi < 4; mi++)
                #pragma unroll
                for (int ni = 0; ni < 4; ni++)
                    mma16(acc[mi][ni], af[mi], bf[ni]);
        }
        __syncthreads();
        if (c + 2 < NC) issue((c + 2) % NST, (c + 2) * KC);
        CP_COMMIT();
        st = (st + 1) % NST;
    }

    // ---- epilogue: (c0,c1)=(F,G) at row t; (c2,c3) at t+8 -------------------
    __half* __restrict__ zb = g_zT + (size_t)b * TT * CC;
    #pragma unroll
    for (int mi = 0; mi < 4; mi++) {
        const int t_lo = t0 + wm * 64 + mi * 16 + (lane >> 2);
        #pragma unroll
        for (int ni = 0; ni < 4; ni++) {
            const int ch = (n0 >> 1) + wn * 16 + ni * 4 + (lane & 3);
            const float fb = fbias[ch], gb = gbias[ch];
            float F0 = acc[mi][ni][0] + fb;
            float G0 = acc[mi][ni][1] + gb;
            float F1 = acc[mi][ni][2] + fb;
            float G1 = acc[mi][ni][3] + gb;
            zb[(size_t)t_lo * CC + ch] =
                __float2half_rn(tanhf(F0) * (1.f / (1.f + __expf(-G0))));
            zb[(size_t)(t_lo + 8) * CC + ch] =
                __float2half_rn(tanhf(F1) * (1.f / (1.f + __expf(-G1))));
        }
    }
}

// ---------------- GEMM2: D[m][t] = W2 @ zT^T, fused residual/skip -----------
// CTA 128(m) x 128(t); 8 warps 2x4; warp tile 64x32. fp16 MMA.
__global__ void __launch_bounds__(256, 2)
gemm2(const float* __restrict__ x,
      const float* __restrict__ rbias, const float* __restrict__ sbias,
      float* __restrict__ out)
{
    extern __shared__ __half hsm[];
    __half* sA = hsm;
    __half* sB = hsm + NST * STAGE;

    const int tid = threadIdx.x, lane = tid & 31, wid = tid >> 5;
    const int wm = wid >> 2, wn = wid & 3;
    const int mb = blockIdx.x;                    // 6 m-tiles
    const int tb = blockIdx.y;                    // 512 t-tiles
    const int base = tb * 128;
    const int b = base / TT;
    const int t0 = base % TT;
    const int m0 = mb * 128;
    const __half* __restrict__ zTb = g_zT + (size_t)b * TT * CC;

    const uint32_t sA_u = (uint32_t)__cvta_generic_to_shared(sA);
    const uint32_t sB_u = (uint32_t)__cvta_generic_to_shared(sB);

    float acc[4][4][4];
    #pragma unroll
    for (int i = 0; i < 4; i++)
        #pragma unroll
        for (int j = 0; j < 4; j++)
            #pragma unroll
            for (int q = 0; q < 4; q++) acc[i][j][q] = 0.f;

    const int arow = tid >> 3, ac8 = (tid & 7) * 8;
    auto issue = [&](int st, int k0) {
        #pragma unroll
        for (int i = 0; i < 4; i++) {
            int row = arow + i * 32;
            cpa16(sA_u + (st * STAGE + row * HST + ac8) * 2,
                  &g_W2[(size_t)(m0 + row) * CC + k0 + ac8]);
            cpa16(sB_u + (st * STAGE + row * HST + ac8) * 2,
                  &zTb[(size_t)(t0 + row) * CC + k0 + ac8]);
        }
    };

    issue(0, 0);  CP_COMMIT();
    issue(1, KC); CP_COMMIT();

    const int aoff = (wm * 64 + (lane >> 2)) * HST + (lane & 3) * 2;
    const int boff = (wn * 32 + (lane >> 2)) * HST + (lane & 3) * 2;

    const int NC = CC / KC;   // 8
    int st = 0;
    for (int c = 0; c < NC; c++) {
        CP_WAIT1();
        __syncthreads();
        const __half* a  = sA + st * STAGE + aoff;
        const __half* bs = sB + st * STAGE + boff;
        #pragma unroll
        for (int ks = 0; ks < 4; ks++) {
            const int kc = ks * 16;
            uint32_t af[4][4], bf[4][2];
            #pragma unroll
            for (int mi = 0; mi < 4; mi++) {
                const __half* p = a + mi * 16 * HST + kc;
                af[mi][0] = *(const uint32_t*)(p);
                af[mi][1] = *(const uint32_t*)(p + 8 * HST);
                af[mi][2] = *(const uint32_t*)(p + 8);
                af[mi][3] = *(const uint32_t*)(p + 8 * HST + 8);
            }
            #pragma unroll
            for (int ni = 0; ni < 4; ni++) {
                const __half* p = bs + ni * 8 * HST + kc;
                bf[ni][0] = *(const uint32_t*)(p);
                bf[ni][1] = *(const uint32_t*)(p + 8);
            }
            #pragma unroll
            for (int mi = 0; mi < 4; mi++)
                #pragma unroll
                for (int ni = 0; ni < 4; ni++)
                    mma16(acc[mi][ni], af[mi], bf[ni]);
        }
        __syncthreads();
        if (c + 2 < NC) issue((c + 2) % NST, (c + 2) * KC);
        CP_COMMIT();
        st = (st + 1) % NST;
    }

    // ---- epilogue: rows m (channels), cols t ---------------------------------
    #pragma unroll
    for (int mi = 0; mi < 4; mi++) {
        #pragma unroll
        for (int half = 0; half < 2; half++) {
            const int m = m0 + wm * 64 + mi * 16 + (lane >> 2) + half * 8;
            if (m < CC) {
                const float rbv = rbias[m];
                const float* __restrict__ xrow = x + ((size_t)b * CC + m) * TT;
                float* __restrict__ orow = out + ((size_t)b * CC + m) * TT;
                #pragma unroll
                for (int ni = 0; ni < 4; ni++) {
                    const int t = t0 + wn * 32 + ni * 8 + (lane & 3) * 2;
                    float2 xv = *(const float2*)&xrow[t];
                    float2 o;
                    o.x = (xv.x + acc[mi][ni][half * 2]     + rbv) * SQRT_HALF;
                    o.y = (xv.y + acc[mi][ni][half * 2 + 1] + rbv) * SQRT_HALF;
                    *(float2*)&orow[t] = o;
                }
            } else {
                const int s = m - CC;
                const float sbv = sbias[s];
                float* __restrict__ orow =
                    out + (size_t)BB * CC * TT + ((size_t)b * SS + s) * TT;
                #pragma unroll
                for (int ni = 0; ni < 4; ni++) {
                    const int t = t0 + wn * 32 + ni * 8 + (lane & 3) * 2;
                    float2 o;
                    o.x = acc[mi][ni][half * 2]     + sbv;
                    o.y = acc[mi][ni][half * 2 + 1] + sbv;
                    *(float2*)&orow[t] = o;
                }
            }
        }
    }
}

// ---------------- launch -----------------------------------------------------
extern "C" void kernel_launch(void* const* d_in, const int* in_sizes, int n_in,
                              void* d_out, int out_size)
{
    const float* x  = (const float*)d_in[0];
    const float* fw = (const float*)d_in[1];
    const float* fb = (const float*)d_in[2];
    const float* gw = (const float*)d_in[3];
    const float* gb = (const float*)d_in[4];
    const float* rw = (const float*)d_in[5];
    const float* rb = (const float*)d_in[6];
    const float* sw = (const float*)d_in[7];
    const float* sb = (const float*)d_in[8];
    float* out = (float*)d_out;

    cudaFuncSetAttribute(gemm1, cudaFuncAttributeMaxDynamicSharedMemorySize, SMEM_DYN);
    cudaFuncSetAttribute(gemm2, cudaFuncAttributeMaxDynamicSharedMemorySize, SMEM_DYN);

    transpose_x<<<dim3(TT / 32, CC / 32, BB), dim3(32, 8)>>>(x);
    pack_w1<<<(M1 * K1 + 255) / 256, 256>>>(fw, gw);
    pack_w2<<<(M2 * CC + 255) / 256, 256>>>(rw, sw);
    gemm1<<<dim3(M1 / 128, NTOT / 128), 256, SMEM_DYN>>>(fb, gb);
    gemm2<<<dim3(M2 / 128, NTOT / 128), 256, SMEM_DYN>>>(x, rb, sb, out);
}